// round 10
// baseline (speedup 1.0000x reference)
#include <cuda_runtime.h>
#include <cuda_bf16.h>
#include <cstdint>
#include <cstddef>

// ---------------- problem constants ----------------
#define BDIM   4096
#define INDIM  2048
#define OUTDIM 2048
#define NCOEFF 8
#define KTOT   18432              // INDIM + INDIM*NCOEFF
#define NKT    288                // KTOT / 64

// ---------------- GEMM tiling (shared by both paths) ----------------
#define BM 128
#define BN 128
#define BK 64                     // 64 bf16 = 128 B = one SW128 row
#define NSTG 3
#define STG_BYTES   49152         // Ahi 16K + Alo 16K + W 16K
#define STG_ALO_OFF 16384
#define STG_B_OFF   32768
#define SMEM_BYTES  (2048 + NSTG * STG_BYTES)   // 149504

// ---------------- device scratch (static globals; no runtime alloc) ----------------
__device__ __align__(128) __nv_bfloat16 g_Ahi[(size_t)BDIM * KTOT];
__device__ __align__(128) __nv_bfloat16 g_Alo[(size_t)BDIM * KTOT];
__device__ __align__(128) __nv_bfloat16 g_W[(size_t)OUTDIM * KTOT];

// ---------------- arch-feature detection ----------------
#if defined(__CUDA_ARCH_FEAT_SM103_ALL) || defined(__CUDA_ARCH_FEAT_SM100_ALL) || \
    (defined(__CUDA_ARCH_SPECIFIC__) && defined(__CUDA_ARCH__) && __CUDA_ARCH__ >= 1000)
#define HAS_TC 1
#else
#define HAS_TC 0
#endif

// ---------------- common PTX helpers (baseline-PTX safe) ----------------
__device__ __forceinline__ uint32_t smem_u32(const void* p) {
    uint32_t a;
    asm("{ .reg .u64 t; cvta.to.shared.u64 t, %1; cvt.u32.u64 %0, t; }" : "=r"(a) : "l"(p));
    return a;
}
__device__ __forceinline__ void cp_async16(uint32_t dst, const void* src) {
    asm volatile("cp.async.cg.shared.global [%0], [%1], 16;" :: "r"(dst), "l"(src) : "memory");
}
#define CP_COMMIT()  asm volatile("cp.async.commit_group;" ::: "memory")
#define CP_WAIT1()   asm volatile("cp.async.wait_group 1;" ::: "memory")

// ---------------- prep: weights -> bf16 [OUT, KTOT] ----------------
__global__ void wprep_kernel(const float* __restrict__ bw, const float* __restrict__ sw) {
    size_t e = ((size_t)blockIdx.x * blockDim.x + threadIdx.x) * 4;
    if (e >= (size_t)OUTDIM * KTOT) return;
    size_t o = e / KTOT;
    size_t k = e - o * KTOT;
    float4 v;
    if (k < INDIM) {
        v = *(const float4*)(bw + o * INDIM + k);
    } else {
        v = *(const float4*)(sw + o * (size_t)(INDIM * NCOEFF) + (k - INDIM));
        v.x = rintf(v.x * 32.f) * 0.03125f;
        v.y = rintf(v.y * 32.f) * 0.03125f;
        v.z = rintf(v.z * 32.f) * 0.03125f;
        v.w = rintf(v.w * 32.f) * 0.03125f;
    }
    __nv_bfloat16 h[4];
    h[0] = __float2bfloat16(v.x); h[1] = __float2bfloat16(v.y);
    h[2] = __float2bfloat16(v.z); h[3] = __float2bfloat16(v.w);
    *(uint2*)(g_W + e) = *(const uint2*)h;
}

// ---------------- prep: x + cubic b-spline basis -> two bf16 planes ----------------
__global__ void aprep_kernel(const float* __restrict__ x, const float* __restrict__ grid) {
    int idx = blockIdx.x * blockDim.x + threadIdx.x;
    if (idx >= BDIM * INDIM) return;
    int b = idx / INDIM;
    int i = idx - b * INDIM;
    float xv = x[idx];
    float g[12];
#pragma unroll
    for (int j = 0; j < 12; ++j) g[j] = grid[i * 12 + j];

    float b0[11];
#pragma unroll
    for (int j = 0; j < 11; ++j) b0[j] = (xv >= g[j] && xv < g[j + 1]) ? 1.f : 0.f;
    float b1[10];
#pragma unroll
    for (int j = 0; j < 10; ++j)
        b1[j] = (xv - g[j]) / (g[j + 1] - g[j] + 1e-8f) * b0[j]
              + (g[j + 2] - xv) / (g[j + 2] - g[j + 1] + 1e-8f) * b0[j + 1];
    float b2[9];
#pragma unroll
    for (int j = 0; j < 9; ++j)
        b2[j] = (xv - g[j]) / (g[j + 2] - g[j] + 1e-8f) * b1[j]
              + (g[j + 3] - xv) / (g[j + 3] - g[j + 1] + 1e-8f) * b1[j + 1];
    float b3[8];
#pragma unroll
    for (int j = 0; j < 8; ++j)
        b3[j] = (xv - g[j]) / (g[j + 3] - g[j] + 1e-8f) * b2[j]
              + (g[j + 4] - xv) / (g[j + 4] - g[j + 1] + 1e-8f) * b2[j + 1];

    size_t rowoff = (size_t)b * KTOT;
    __nv_bfloat16 xh = __float2bfloat16(xv);
    g_Ahi[rowoff + i] = xh;
    g_Alo[rowoff + i] = __float2bfloat16(xv - __bfloat162float(xh));

    __nv_bfloat16 hi[8], lo[8];
#pragma unroll
    for (int c = 0; c < 8; ++c) {
        hi[c] = __float2bfloat16(b3[c]);
        lo[c] = __float2bfloat16(b3[c] - __bfloat162float(hi[c]));
    }
    size_t boff = rowoff + INDIM + (size_t)i * 8;
    *(uint4*)(g_Ahi + boff) = *(const uint4*)hi;
    *(uint4*)(g_Alo + boff) = *(const uint4*)lo;
}

// ---------------- stage loader: Ahi/Alo/W, 128 rows x 128B each, SW128 swizzled ----------------
__device__ __forceinline__ void load_stage(int kt, int m0, int o0, uint32_t stg, int tid) {
    size_t kcol = (size_t)kt * BK;
#pragma unroll
    for (int it = 0; it < 4; ++it) {
        int idx = tid + it * 256;              // 1024 16B-chunks per tile
        int r = idx >> 3, c = idx & 7;
        uint32_t off = (uint32_t)(r * 128 + c * 16);
        uint32_t sw = off ^ ((off >> 3) & 0x70);
        size_t goffA = (size_t)(m0 + r) * KTOT + kcol + (size_t)c * 8;
        cp_async16(stg + sw, g_Ahi + goffA);
        cp_async16(stg + STG_ALO_OFF + sw, g_Alo + goffA);
        cp_async16(stg + STG_B_OFF + sw,
                   g_W + (size_t)(o0 + r) * KTOT + kcol + (size_t)c * 8);
    }
}

#if HAS_TC
// ================= tcgen05 path helpers =================
__device__ __forceinline__ uint32_t elect1() {
    uint32_t r;
    asm volatile("{ .reg .pred p; elect.sync _|p, 0xFFFFFFFF; selp.b32 %0, 1, 0, p; }" : "=r"(r));
    return r;
}
__device__ __forceinline__ void mbar_init(uint32_t a, uint32_t cnt) {
    asm volatile("mbarrier.init.shared.b64 [%0], %1;" :: "r"(a), "r"(cnt) : "memory");
}
__device__ __forceinline__ void mbar_wait(uint32_t a, uint32_t parity) {
    asm volatile(
        "{\n\t.reg .pred P1;\n\t"
        "W_%=:\n\t"
        "mbarrier.try_wait.parity.acquire.cta.shared::cta.b64 P1, [%0], %1, 0x989680;\n\t"
        "@P1 bra.uni D_%=;\n\t"
        "bra.uni W_%=;\n\t"
        "D_%=:\n\t}"
        :: "r"(a), "r"(parity) : "memory");
}
__device__ __forceinline__ uint64_t mk_desc(uint32_t addr) {
    return ((uint64_t)2 << 61) | ((uint64_t)1 << 46) | ((uint64_t)64 << 32)
         | ((uint64_t)1 << 16) | ((uint64_t)(addr >> 4) & 0x3FFF);
}
#define IDESC 0x08200490u   // F32 accum, bf16 x bf16, N=128, M=128
__device__ __forceinline__ void mma_f16_ss(uint32_t d, uint64_t a, uint64_t b, uint32_t en) {
    asm volatile(
        "{\n\t.reg .pred p;\n\tsetp.ne.u32 p, %4, 0;\n\t"
        "tcgen05.mma.cta_group::1.kind::f16 [%0], %1, %2, %3, {%5,%5,%5,%5}, p;\n\t}"
        :: "r"(d), "l"(a), "l"(b), "r"(IDESC), "r"(en), "r"(0u) : "memory");
}
__device__ __forceinline__ void tmem_ld32(uint32_t* r, uint32_t addr) {
    asm volatile(
        "tcgen05.ld.sync.aligned.32x32b.x32.b32 "
        "{%0, %1, %2, %3, %4, %5, %6, %7, "
        " %8, %9, %10, %11, %12, %13, %14, %15, "
        " %16, %17, %18, %19, %20, %21, %22, %23, "
        " %24, %25, %26, %27, %28, %29, %30, %31}, [%32];"
        : "=r"(r[0]),  "=r"(r[1]),  "=r"(r[2]),  "=r"(r[3]),
          "=r"(r[4]),  "=r"(r[5]),  "=r"(r[6]),  "=r"(r[7]),
          "=r"(r[8]),  "=r"(r[9]),  "=r"(r[10]), "=r"(r[11]),
          "=r"(r[12]), "=r"(r[13]), "=r"(r[14]), "=r"(r[15]),
          "=r"(r[16]), "=r"(r[17]), "=r"(r[18]), "=r"(r[19]),
          "=r"(r[20]), "=r"(r[21]), "=r"(r[22]), "=r"(r[23]),
          "=r"(r[24]), "=r"(r[25]), "=r"(r[26]), "=r"(r[27]),
          "=r"(r[28]), "=r"(r[29]), "=r"(r[30]), "=r"(r[31])
        : "r"(addr));
}
#else
// ================= HMMA fallback helpers (baseline PTX) =================
__device__ __forceinline__ void ldsm_x4(uint32_t* r, uint32_t addr) {
    asm volatile("ldmatrix.sync.aligned.m8n8.x4.shared.b16 {%0,%1,%2,%3}, [%4];"
                 : "=r"(r[0]), "=r"(r[1]), "=r"(r[2]), "=r"(r[3]) : "r"(addr));
}
__device__ __forceinline__ void ldsm_x4_t(uint32_t* r, uint32_t addr) {
    asm volatile("ldmatrix.sync.aligned.m8n8.x4.trans.shared.b16 {%0,%1,%2,%3}, [%4];"
                 : "=r"(r[0]), "=r"(r[1]), "=r"(r[2]), "=r"(r[3]) : "r"(addr));
}
__device__ __forceinline__ void mma_bf16(float* c, const uint32_t* a, uint32_t b0, uint32_t b1) {
    asm volatile(
        "mma.sync.aligned.m16n8k16.row.col.f32.bf16.bf16.f32 "
        "{%0,%1,%2,%3}, {%4,%5,%6,%7}, {%8,%9}, {%0,%1,%2,%3};"
        : "+f"(c[0]), "+f"(c[1]), "+f"(c[2]), "+f"(c[3])
        : "r"(a[0]), "r"(a[1]), "r"(a[2]), "r"(a[3]), "r"(b0), "r"(b1));
}
#endif

// ---------------- GEMM: C[4096,2048] = Ahi@W^T + Alo@W^T (fp32 accum) ----------------
__global__ void __launch_bounds__(256, 1)
gemm_kernel(float* __restrict__ out) {
    extern __shared__ char smem[];
    uint32_t sb = smem_u32(smem);
    uint32_t tiles = (sb + 64 + 1023) & ~1023u;
    int tid = threadIdx.x;
    int wid = tid >> 5;
    int lane = tid & 31;
    int m0 = blockIdx.y * BM;
    int o0 = blockIdx.x * BN;

#if HAS_TC
    if (wid == 0)
        asm volatile("tcgen05.alloc.cta_group::1.sync.aligned.shared::cta.b32 [%0], %1;"
                     :: "r"(sb), "r"(128u) : "memory");
    if (tid == 0) { mbar_init(sb + 8, 1); mbar_init(sb + 16, 1); }
    __syncthreads();
    uint32_t tmem;
    asm volatile("ld.shared.b32 %0, [%1];" : "=r"(tmem) : "r"(sb));

    load_stage(0, m0, o0, tiles, tid); CP_COMMIT();
    load_stage(1, m0, o0, tiles + STG_BYTES, tid); CP_COMMIT();

    uint32_t ph0 = 0, ph1 = 0;
    for (int kt = 0; kt < NKT; ++kt) {
        CP_WAIT1();
        __syncthreads();
        if (wid == 0 && elect1()) {
            asm volatile("fence.proxy.async.shared::cta;" ::: "memory");
            uint32_t stg = tiles + (uint32_t)(kt % NSTG) * STG_BYTES;
            uint64_t dahi = mk_desc(stg);
            uint64_t dalo = mk_desc(stg + STG_ALO_OFF);
            uint64_t dw   = mk_desc(stg + STG_B_OFF);
#pragma unroll
            for (int ks = 0; ks < 4; ++ks) {
                uint64_t d = (uint64_t)(ks * 2);
                mma_f16_ss(tmem, dahi + d, dw + d, (kt == 0 && ks == 0) ? 0u : 1u);
                mma_f16_ss(tmem, dalo + d, dw + d, 1u);
            }
            asm volatile(
                "tcgen05.commit.cta_group::1.mbarrier::arrive::one.shared::cluster.b64 [%0];"
                :: "r"(sb + 8 + (uint32_t)(kt & 1) * 8) : "memory");
        }
        if (kt > 0) {
            if ((kt - 1) & 1) { mbar_wait(sb + 16, ph1); ph1 ^= 1; }
            else              { mbar_wait(sb + 8,  ph0); ph0 ^= 1; }
        }
        if (kt + 2 < NKT)
            load_stage(kt + 2, m0, o0, tiles + (uint32_t)((kt + 2) % NSTG) * STG_BYTES, tid);
        CP_COMMIT();
    }
    if ((NKT - 1) & 1) mbar_wait(sb + 16, ph1);
    else               mbar_wait(sb + 8,  ph0);
    asm volatile("tcgen05.fence::after_thread_sync;" ::: "memory");

    // epilogue: warp w -> rows (w&3)*32+lane, cols (w>>2)*64 .. +63
    {
        int sub = wid & 3;
        int colbase = (wid >> 2) * 64;
        float* orow = out + (size_t)(m0 + sub * 32 + lane) * OUTDIM + o0 + colbase;
#pragma unroll
        for (int ch = 0; ch < 2; ++ch) {
            uint32_t r[32];
            tmem_ld32(r, tmem + (uint32_t)(colbase + ch * 32));
            asm volatile("tcgen05.wait::ld.sync.aligned;" ::: "memory");
#pragma unroll
            for (int q = 0; q < 8; ++q) {
                float4 v;
                v.x = __uint_as_float(r[q * 4 + 0]);
                v.y = __uint_as_float(r[q * 4 + 1]);
                v.z = __uint_as_float(r[q * 4 + 2]);
                v.w = __uint_as_float(r[q * 4 + 3]);
                *(float4*)(orow + ch * 32 + q * 4) = v;
            }
        }
    }
    asm volatile("tcgen05.fence::before_thread_sync;" ::: "memory");
    __syncthreads();
    if (wid == 0) {
        asm volatile("tcgen05.relinquish_alloc_permit.cta_group::1.sync.aligned;");
        asm volatile("tcgen05.dealloc.cta_group::1.sync.aligned.b32 %0, %1;"
                     :: "r"(tmem), "r"(128u));
    }
#else
    // ---- HMMA fallback: 8 warps, warp tile 64x32 (2x4 grid over 128x128) ----
    int wm = (wid >> 2) * 64;
    int wn = (wid & 3) * 32;
    float acc[4][4][4];
#pragma unroll
    for (int mi = 0; mi < 4; ++mi)
#pragma unroll
        for (int nj = 0; nj < 4; ++nj)
#pragma unroll
            for (int q = 0; q < 4; ++q) acc[mi][nj][q] = 0.f;

    load_stage(0, m0, o0, tiles, tid); CP_COMMIT();
    load_stage(1, m0, o0, tiles + STG_BYTES, tid); CP_COMMIT();

    int lrow = lane & 15;
    int lcolb = (lane >> 4) << 4;
    for (int kt = 0; kt < NKT; ++kt) {
        CP_WAIT1();
        __syncthreads();
        uint32_t stg = tiles + (uint32_t)(kt % NSTG) * STG_BYTES;
#pragma unroll
        for (int ks = 0; ks < 4; ++ks) {
            int kb = ks * 32 + lcolb;
            uint32_t bf[8];
#pragma unroll
            for (int ni = 0; ni < 2; ++ni) {
                uint32_t off = (uint32_t)((wn + ni * 16 + lrow) * 128 + kb);
                off ^= (off >> 3) & 0x70;
                ldsm_x4_t(bf + ni * 4, stg + STG_B_OFF + off);
            }
#pragma unroll
            for (int mi = 0; mi < 4; ++mi) {
                uint32_t off = (uint32_t)((wm + mi * 16 + lrow) * 128 + kb);
                off ^= (off >> 3) & 0x70;
                uint32_t a[4];
                ldsm_x4(a, stg + off);          // hi plane
#pragma unroll
                for (int nj = 0; nj < 4; ++nj)
                    mma_bf16(acc[mi][nj], a,
                             bf[(nj >> 1) * 4 + (nj & 1)], bf[(nj >> 1) * 4 + (nj & 1) + 2]);
                ldsm_x4(a, stg + STG_ALO_OFF + off);   // lo plane
#pragma unroll
                for (int nj = 0; nj < 4; ++nj)
                    mma_bf16(acc[mi][nj], a,
                             bf[(nj >> 1) * 4 + (nj & 1)], bf[(nj >> 1) * 4 + (nj & 1) + 2]);
            }
        }
        if (kt + 2 < NKT)
            load_stage(kt + 2, m0, o0, tiles + (uint32_t)((kt + 2) % NSTG) * STG_BYTES, tid);
        CP_COMMIT();
    }

    // epilogue: mma C layout -> rows lane/4 (+8), cols (lane%4)*2 (+1)
#pragma unroll
    for (int mi = 0; mi < 4; ++mi) {
#pragma unroll
        for (int nj = 0; nj < 4; ++nj) {
            size_t row = (size_t)(m0 + wm + mi * 16 + (lane >> 2));
            size_t col = (size_t)(o0 + wn + nj * 8 + (lane & 3) * 2);
            float2 v0 = make_float2(acc[mi][nj][0], acc[mi][nj][1]);
            float2 v1 = make_float2(acc[mi][nj][2], acc[mi][nj][3]);
            *(float2*)(out + row * OUTDIM + col) = v0;
            *(float2*)(out + (row + 8) * OUTDIM + col) = v1;
        }
    }
#endif
}

// ---------------- launcher ----------------
extern "C" void kernel_launch(void* const* d_in, const int* in_sizes, int n_in,
                              void* d_out, int out_size) {
    (void)in_sizes; (void)n_in; (void)out_size;
    const float* x    = (const float*)d_in[0];
    const float* bw   = (const float*)d_in[1];
    const float* sw   = (const float*)d_in[2];
    const float* grid = (const float*)d_in[3];
    float* out = (float*)d_out;

    {
        int total4 = (OUTDIM * KTOT) / 4;
        wprep_kernel<<<(total4 + 255) / 256, 256>>>(bw, sw);
    }
    {
        int total = BDIM * INDIM;
        aprep_kernel<<<(total + 255) / 256, 256>>>(x, grid);
    }
    cudaFuncSetAttribute(gemm_kernel, cudaFuncAttributeMaxDynamicSharedMemorySize, SMEM_BYTES);
    dim3 g(OUTDIM / BN, BDIM / BM);   // (16, 32)
    gemm_kernel<<<g, 256, SMEM_BYTES>>>(out);
}

// round 13
// speedup vs baseline: 1.1145x; 1.1145x over previous
#include <cuda_runtime.h>
#include <cuda_fp16.h>
#include <cstdint>
#include <cstddef>

// ---------------- problem constants ----------------
#define BDIM   4096
#define INDIM  2048
#define OUTDIM 2048
#define NCOEFF 8
#define KTOT   18432              // INDIM + INDIM*NCOEFF
#define NKT    288                // KTOT / 64

// ---------------- GEMM tiling ----------------
#define BM 128
#define BN 128
#define BK 64                     // 64 fp16 = 128 B = one SW128 row
#define NSTG 3
#define STG_BYTES   32768         // A 16K + W 16K
#define STG_B_OFF   16384
#define SMEM_BYTES  (2048 + NSTG * STG_BYTES)   // 100352

// ---------------- device scratch (static globals; no runtime alloc) ----------------
__device__ __align__(128) __half g_A[(size_t)BDIM * KTOT];
__device__ __align__(128) __half g_W[(size_t)OUTDIM * KTOT];

// ---------------- arch-feature detection (same as R10, which passed) ----------------
#if defined(__CUDA_ARCH_FEAT_SM103_ALL) || defined(__CUDA_ARCH_FEAT_SM100_ALL) || \
    (defined(__CUDA_ARCH_SPECIFIC__) && defined(__CUDA_ARCH__) && __CUDA_ARCH__ >= 1000)
#define HAS_TC 1
#else
#define HAS_TC 0
#endif

// ---------------- common PTX helpers (baseline-PTX safe) ----------------
__device__ __forceinline__ uint32_t smem_u32(const void* p) {
    uint32_t a;
    asm("{ .reg .u64 t; cvta.to.shared.u64 t, %1; cvt.u32.u64 %0, t; }" : "=r"(a) : "l"(p));
    return a;
}
__device__ __forceinline__ void cp_async16(uint32_t dst, const void* src) {
    asm volatile("cp.async.cg.shared.global [%0], [%1], 16;" :: "r"(dst), "l"(src) : "memory");
}
#define CP_COMMIT()  asm volatile("cp.async.commit_group;" ::: "memory")
#define CP_WAIT1()   asm volatile("cp.async.wait_group 1;" ::: "memory")

// ---------------- prep: weights -> fp16 [OUT, KTOT] ----------------
__global__ void wprep_kernel(const float* __restrict__ bw, const float* __restrict__ sw) {
    size_t e = ((size_t)blockIdx.x * blockDim.x + threadIdx.x) * 4;
    if (e >= (size_t)OUTDIM * KTOT) return;
    size_t o = e / KTOT;
    size_t k = e - o * KTOT;
    float4 v;
    if (k < INDIM) {
        v = *(const float4*)(bw + o * INDIM + k);
    } else {
        v = *(const float4*)(sw + o * (size_t)(INDIM * NCOEFF) + (k - INDIM));
        v.x = rintf(v.x * 32.f) * 0.03125f;
        v.y = rintf(v.y * 32.f) * 0.03125f;
        v.z = rintf(v.z * 32.f) * 0.03125f;
        v.w = rintf(v.w * 32.f) * 0.03125f;
    }
    __half h[4];
    h[0] = __float2half_rn(v.x); h[1] = __float2half_rn(v.y);
    h[2] = __float2half_rn(v.z); h[3] = __float2half_rn(v.w);
    *(uint2*)(g_W + e) = *(const uint2*)h;
}

// ---------------- prep: x + cubic b-spline basis -> fp16 plane ----------------
__global__ void aprep_kernel(const float* __restrict__ x, const float* __restrict__ grid) {
    int idx = blockIdx.x * blockDim.x + threadIdx.x;
    if (idx >= BDIM * INDIM) return;
    int b = idx / INDIM;
    int i = idx - b * INDIM;
    float xv = x[idx];
    float g[12];
#pragma unroll
    for (int j = 0; j < 12; ++j) g[j] = grid[i * 12 + j];

    float b0[11];
#pragma unroll
    for (int j = 0; j < 11; ++j) b0[j] = (xv >= g[j] && xv < g[j + 1]) ? 1.f : 0.f;
    float b1[10];
#pragma unroll
    for (int j = 0; j < 10; ++j)
        b1[j] = (xv - g[j]) / (g[j + 1] - g[j] + 1e-8f) * b0[j]
              + (g[j + 2] - xv) / (g[j + 2] - g[j + 1] + 1e-8f) * b0[j + 1];
    float b2[9];
#pragma unroll
    for (int j = 0; j < 9; ++j)
        b2[j] = (xv - g[j]) / (g[j + 2] - g[j] + 1e-8f) * b1[j]
              + (g[j + 3] - xv) / (g[j + 3] - g[j + 1] + 1e-8f) * b1[j + 1];
    float b3[8];
#pragma unroll
    for (int j = 0; j < 8; ++j)
        b3[j] = (xv - g[j]) / (g[j + 3] - g[j] + 1e-8f) * b2[j]
              + (g[j + 4] - xv) / (g[j + 4] - g[j + 1] + 1e-8f) * b2[j + 1];

    size_t rowoff = (size_t)b * KTOT;
    g_A[rowoff + i] = __float2half_rn(xv);

    __half h[8];
#pragma unroll
    for (int c = 0; c < 8; ++c) h[c] = __float2half_rn(b3[c]);
    *(uint4*)(g_A + rowoff + INDIM + (size_t)i * 8) = *(const uint4*)h;
}

// ---------------- stage loader: A 128x128B + W 128x128B, SW128 swizzled ----------------
__device__ __forceinline__ void load_stage(int kt, int m0, int o0, uint32_t stg, int tid) {
    size_t kcol = (size_t)kt * BK;
#pragma unroll
    for (int it = 0; it < 4; ++it) {          // 1024 16B-chunks per tile
        int idx = tid + it * 256;
        int r = idx >> 3, c = idx & 7;
        uint32_t off = (uint32_t)(r * 128 + c * 16);
        uint32_t sw = off ^ ((off >> 3) & 0x70);
        cp_async16(stg + sw, g_A + (size_t)(m0 + r) * KTOT + kcol + (size_t)c * 8);
        cp_async16(stg + STG_B_OFF + sw,
                   g_W + (size_t)(o0 + r) * KTOT + kcol + (size_t)c * 8);
    }
}

#if HAS_TC
// ================= tcgen05 path helpers (R10-validated) =================
__device__ __forceinline__ uint32_t elect1() {
    uint32_t r;
    asm volatile("{ .reg .pred p; elect.sync _|p, 0xFFFFFFFF; selp.b32 %0, 1, 0, p; }" : "=r"(r));
    return r;
}
__device__ __forceinline__ void mbar_init(uint32_t a, uint32_t cnt) {
    asm volatile("mbarrier.init.shared.b64 [%0], %1;" :: "r"(a), "r"(cnt) : "memory");
}
__device__ __forceinline__ void mbar_wait(uint32_t a, uint32_t parity) {
    asm volatile(
        "{\n\t.reg .pred P1;\n\t"
        "W_%=:\n\t"
        "mbarrier.try_wait.parity.acquire.cta.shared::cta.b64 P1, [%0], %1, 0x989680;\n\t"
        "@P1 bra.uni D_%=;\n\t"
        "bra.uni W_%=;\n\t"
        "D_%=:\n\t}"
        :: "r"(a), "r"(parity) : "memory");
}
__device__ __forceinline__ uint64_t mk_desc(uint32_t addr) {
    return ((uint64_t)2 << 61) | ((uint64_t)1 << 46) | ((uint64_t)64 << 32)
         | ((uint64_t)1 << 16) | ((uint64_t)(addr >> 4) & 0x3FFF);
}
#define IDESC 0x08200010u   // F32 accum, f16 x f16, N=128, M=128
__device__ __forceinline__ void mma_f16_ss(uint32_t d, uint64_t a, uint64_t b, uint32_t en) {
    asm volatile(
        "{\n\t.reg .pred p;\n\tsetp.ne.u32 p, %4, 0;\n\t"
        "tcgen05.mma.cta_group::1.kind::f16 [%0], %1, %2, %3, {%5,%5,%5,%5}, p;\n\t}"
        :: "r"(d), "l"(a), "l"(b), "r"(IDESC), "r"(en), "r"(0u) : "memory");
}
__device__ __forceinline__ void tmem_ld32(uint32_t* r, uint32_t addr) {
    asm volatile(
        "tcgen05.ld.sync.aligned.32x32b.x32.b32 "
        "{%0, %1, %2, %3, %4, %5, %6, %7, "
        " %8, %9, %10, %11, %12, %13, %14, %15, "
        " %16, %17, %18, %19, %20, %21, %22, %23, "
        " %24, %25, %26, %27, %28, %29, %30, %31}, [%32];"
        : "=r"(r[0]),  "=r"(r[1]),  "=r"(r[2]),  "=r"(r[3]),
          "=r"(r[4]),  "=r"(r[5]),  "=r"(r[6]),  "=r"(r[7]),
          "=r"(r[8]),  "=r"(r[9]),  "=r"(r[10]), "=r"(r[11]),
          "=r"(r[12]), "=r"(r[13]), "=r"(r[14]), "=r"(r[15]),
          "=r"(r[16]), "=r"(r[17]), "=r"(r[18]), "=r"(r[19]),
          "=r"(r[20]), "=r"(r[21]), "=r"(r[22]), "=r"(r[23]),
          "=r"(r[24]), "=r"(r[25]), "=r"(r[26]), "=r"(r[27]),
          "=r"(r[28]), "=r"(r[29]), "=r"(r[30]), "=r"(r[31])
        : "r"(addr));
}
#else
// ================= HMMA fallback helpers (baseline PTX) =================
__device__ __forceinline__ void ldsm_x4(uint32_t* r, uint32_t addr) {
    asm volatile("ldmatrix.sync.aligned.m8n8.x4.shared.b16 {%0,%1,%2,%3}, [%4];"
                 : "=r"(r[0]), "=r"(r[1]), "=r"(r[2]), "=r"(r[3]) : "r"(addr));
}
__device__ __forceinline__ void mma_fp16(float* c, const uint32_t* a, uint32_t b0, uint32_t b1) {
    asm volatile(
        "mma.sync.aligned.m16n8k16.row.col.f32.f16.f16.f32 "
        "{%0,%1,%2,%3}, {%4,%5,%6,%7}, {%8,%9}, {%0,%1,%2,%3};"
        : "+f"(c[0]), "+f"(c[1]), "+f"(c[2]), "+f"(c[3])
        : "r"(a[0]), "r"(a[1]), "r"(a[2]), "r"(a[3]), "r"(b0), "r"(b1));
}
#endif

// ---------------- GEMM: C[4096,2048] = A @ W^T, fp32 accum ----------------
__global__ void __launch_bounds__(256, 1)
gemm_kernel(float* __restrict__ out) {
    extern __shared__ char smem[];
    uint32_t sb = smem_u32(smem);
    uint32_t tiles = (sb + 64 + 1023) & ~1023u;   // ctrl words stay below tiles
    int tid = threadIdx.x;
    int wid = tid >> 5;
    int lane = tid & 31;
    int m0 = blockIdx.y * BM;
    int o0 = blockIdx.x * BN;

#if HAS_TC
    if (wid == 0)
        asm volatile("tcgen05.alloc.cta_group::1.sync.aligned.shared::cta.b32 [%0], %1;"
                     :: "r"(sb), "r"(128u) : "memory");
    if (tid == 0) { mbar_init(sb + 8, 1); mbar_init(sb + 16, 1); }
    __syncthreads();
    uint32_t tmem;
    asm volatile("ld.shared.b32 %0, [%1];" : "=r"(tmem) : "r"(sb));

    load_stage(0, m0, o0, tiles, tid); CP_COMMIT();
    load_stage(1, m0, o0, tiles + STG_BYTES, tid); CP_COMMIT();

    uint32_t ph0 = 0, ph1 = 0;
    for (int kt = 0; kt < NKT; ++kt) {
        CP_WAIT1();
        __syncthreads();
        if (wid == 0 && elect1()) {
            asm volatile("fence.proxy.async.shared::cta;" ::: "memory");
            uint32_t stg = tiles + (uint32_t)(kt % NSTG) * STG_BYTES;
            uint64_t da = mk_desc(stg);
            uint64_t dw = mk_desc(stg + STG_B_OFF);
#pragma unroll
            for (int ks = 0; ks < 4; ++ks) {
                uint64_t d = (uint64_t)(ks * 2);
                mma_f16_ss(tmem, da + d, dw + d, (kt == 0 && ks == 0) ? 0u : 1u);
            }
            asm volatile(
                "tcgen05.commit.cta_group::1.mbarrier::arrive::one.shared::cluster.b64 [%0];"
                :: "r"(sb + 8 + (uint32_t)(kt & 1) * 8) : "memory");
        }
        if (kt > 0) {
            if ((kt - 1) & 1) { mbar_wait(sb + 16, ph1); ph1 ^= 1; }
            else              { mbar_wait(sb + 8,  ph0); ph0 ^= 1; }
        }
        if (kt + 2 < NKT)
            load_stage(kt + 2, m0, o0, tiles + (uint32_t)((kt + 2) % NSTG) * STG_BYTES, tid);
        CP_COMMIT();
    }
    if ((NKT - 1) & 1) mbar_wait(sb + 16, ph1);
    else               mbar_wait(sb + 8,  ph0);
    asm volatile("tcgen05.fence::after_thread_sync;" ::: "memory");

    // epilogue: warp w -> rows (w&3)*32+lane, cols (w>>2)*64 .. +63
    {
        int sub = wid & 3;
        int colbase = (wid >> 2) * 64;
        float* orow = out + (size_t)(m0 + sub * 32 + lane) * OUTDIM + o0 + colbase;
#pragma unroll
        for (int ch = 0; ch < 2; ++ch) {
            uint32_t r[32];
            tmem_ld32(r, tmem + (uint32_t)(colbase + ch * 32));
            asm volatile("tcgen05.wait::ld.sync.aligned;" ::: "memory");
#pragma unroll
            for (int q = 0; q < 8; ++q) {
                float4 v;
                v.x = __uint_as_float(r[q * 4 + 0]);
                v.y = __uint_as_float(r[q * 4 + 1]);
                v.z = __uint_as_float(r[q * 4 + 2]);
                v.w = __uint_as_float(r[q * 4 + 3]);
                *(float4*)(orow + ch * 32 + q * 4) = v;
            }
        }
    }
    asm volatile("tcgen05.fence::before_thread_sync;" ::: "memory");
    __syncthreads();
    if (wid == 0) {
        asm volatile("tcgen05.relinquish_alloc_permit.cta_group::1.sync.aligned;");
        asm volatile("tcgen05.dealloc.cta_group::1.sync.aligned.b32 %0, %1;"
                     :: "r"(tmem), "r"(128u));
    }
#else
    // ---- HMMA fallback: warp tile 64x32, warp grid 2x4 (B via NON-trans ldmatrix) ----
    int wm = (wid >> 2) * 64;
    int wn = (wid & 3) * 32;
    float acc[4][4][4];
#pragma unroll
    for (int mi = 0; mi < 4; ++mi)
#pragma unroll
        for (int nj = 0; nj < 4; ++nj)
#pragma unroll
            for (int q = 0; q < 4; ++q) acc[mi][nj][q] = 0.f;

    load_stage(0, m0, o0, tiles, tid); CP_COMMIT();
    load_stage(1, m0, o0, tiles + STG_BYTES, tid); CP_COMMIT();

    int lrow = lane & 15;
    int lcolb = (lane >> 4) << 4;
    for (int kt = 0; kt < NKT; ++kt) {
        CP_WAIT1();
        __syncthreads();
        uint32_t stg = tiles + (uint32_t)(kt % NSTG) * STG_BYTES;
#pragma unroll
        for (int ks = 0; ks < 4; ++ks) {
            int kb = ks * 32 + lcolb;
            uint32_t bf[8];
#pragma unroll
            for (int ni = 0; ni < 2; ++ni) {
                uint32_t off = (uint32_t)((wn + ni * 16 + lrow) * 128 + kb);
                off ^= (off >> 3) & 0x70;
                ldsm_x4(bf + ni * 4, stg + STG_B_OFF + off);   // NON-trans: W is n-major
            }
#pragma unroll
            for (int mi = 0; mi < 4; ++mi) {
                uint32_t off = (uint32_t)((wm + mi * 16 + lrow) * 128 + kb);
                off ^= (off >> 3) & 0x70;
                uint32_t a[4];
                ldsm_x4(a, stg + off);
#pragma unroll
                for (int nj = 0; nj < 4; ++nj)
                    mma_fp16(acc[mi][nj], a,
                             bf[(nj >> 1) * 4 + (nj & 1)], bf[(nj >> 1) * 4 + (nj & 1) + 2]);
            }
        }
        if (kt + 2 < NKT)
            load_stage(kt + 2, m0, o0, tiles + (uint32_t)((kt + 2) % NSTG) * STG_BYTES, tid);
        CP_COMMIT();
    }

#pragma unroll
    for (int mi = 0; mi < 4; ++mi) {
#pragma unroll
        for (int nj = 0; nj < 4; ++nj) {
            size_t row = (size_t)(m0 + wm + mi * 16 + (lane >> 2));
            size_t col = (size_t)(o0 + wn + nj * 8 + (lane & 3) * 2);
            *(float2*)(out + row * OUTDIM + col) =
                make_float2(acc[mi][nj][0], acc[mi][nj][1]);
            *(float2*)(out + (row + 8) * OUTDIM + col) =
                make_float2(acc[mi][nj][2], acc[mi][nj][3]);
        }
    }
#endif
}

// ---------------- launcher ----------------
extern "C" void kernel_launch(void* const* d_in, const int* in_sizes, int n_in,
                              void* d_out, int out_size) {
    (void)in_sizes; (void)n_in; (void)out_size;
    const float* x    = (const float*)d_in[0];
    const float* bw   = (const float*)d_in[1];
    const float* sw   = (const float*)d_in[2];
    const float* grid = (const float*)d_in[3];
    float* out = (float*)d_out;

    {
        int total4 = (OUTDIM * KTOT) / 4;
        wprep_kernel<<<(total4 + 255) / 256, 256>>>(bw, sw);
    }
    {
        int total = BDIM * INDIM;
        aprep_kernel<<<(total + 255) / 256, 256>>>(x, grid);
    }
    cudaFuncSetAttribute(gemm_kernel, cudaFuncAttributeMaxDynamicSharedMemorySize, SMEM_BYTES);
    dim3 g(OUTDIM / BN, BDIM / BM);   // (16, 32)
    gemm_kernel<<<g, 256, SMEM_BYTES>>>(out);
}

// round 14
// speedup vs baseline: 1.8674x; 1.6755x over previous
#include <cuda_runtime.h>
#include <cuda_fp16.h>
#include <cstdint>
#include <cstddef>

// ---------------- problem constants ----------------
#define BDIM   4096
#define INDIM  2048
#define OUTDIM 2048
#define NCOEFF 8
#define KTOT   18432              // INDIM + INDIM*NCOEFF
#define NKT    288                // KTOT / 64

// ---------------- GEMM tiling ----------------
#define BM 256
#define BN 256
#define BK 64                     // 64 fp16 = 128 B = one SW128 row
#define NSTG 3
#define STG_BYTES   65536         // A 32K (256 rows) + W 32K (256 rows)
#define STG_B_OFF   32768
#define SMEM_BYTES  (2048 + NSTG * STG_BYTES)   // 198656

// ---------------- device scratch (static globals; no runtime alloc) ----------------
__device__ __align__(128) __half g_A[(size_t)BDIM * KTOT];
__device__ __align__(128) __half g_W[(size_t)OUTDIM * KTOT];

// ---------------- arch-feature detection (R10/R13-proven) ----------------
#if defined(__CUDA_ARCH_FEAT_SM103_ALL) || defined(__CUDA_ARCH_FEAT_SM100_ALL) || \
    (defined(__CUDA_ARCH_SPECIFIC__) && defined(__CUDA_ARCH__) && __CUDA_ARCH__ >= 1000)
#define HAS_TC 1
#else
#define HAS_TC 0
#endif

// ---------------- common PTX helpers (baseline-PTX safe) ----------------
__device__ __forceinline__ uint32_t smem_u32(const void* p) {
    uint32_t a;
    asm("{ .reg .u64 t; cvta.to.shared.u64 t, %1; cvt.u32.u64 %0, t; }" : "=r"(a) : "l"(p));
    return a;
}
__device__ __forceinline__ void cp_async16(uint32_t dst, const void* src) {
    asm volatile("cp.async.cg.shared.global [%0], [%1], 16;" :: "r"(dst), "l"(src) : "memory");
}
#define CP_COMMIT()  asm volatile("cp.async.commit_group;" ::: "memory")
#define CP_WAIT1()   asm volatile("cp.async.wait_group 1;" ::: "memory")

// ---------------- prep: weights -> fp16 [OUT, KTOT] ----------------
__global__ void wprep_kernel(const float* __restrict__ bw, const float* __restrict__ sw) {
    size_t e = ((size_t)blockIdx.x * blockDim.x + threadIdx.x) * 4;
    if (e >= (size_t)OUTDIM * KTOT) return;
    size_t o = e / KTOT;
    size_t k = e - o * KTOT;
    float4 v;
    if (k < INDIM) {
        v = *(const float4*)(bw + o * INDIM + k);
    } else {
        v = *(const float4*)(sw + o * (size_t)(INDIM * NCOEFF) + (k - INDIM));
        v.x = rintf(v.x * 32.f) * 0.03125f;
        v.y = rintf(v.y * 32.f) * 0.03125f;
        v.z = rintf(v.z * 32.f) * 0.03125f;
        v.w = rintf(v.w * 32.f) * 0.03125f;
    }
    __half h[4];
    h[0] = __float2half_rn(v.x); h[1] = __float2half_rn(v.y);
    h[2] = __float2half_rn(v.z); h[3] = __float2half_rn(v.w);
    *(uint2*)(g_W + e) = *(const uint2*)h;
}

// ---------------- prep: x + cubic b-spline basis -> fp16 plane ----------------
__global__ void aprep_kernel(const float* __restrict__ x, const float* __restrict__ grid) {
    int idx = blockIdx.x * blockDim.x + threadIdx.x;
    if (idx >= BDIM * INDIM) return;
    int b = idx / INDIM;
    int i = idx - b * INDIM;
    float xv = x[idx];
    float g[12];
#pragma unroll
    for (int j = 0; j < 12; ++j) g[j] = grid[i * 12 + j];

    float b0[11];
#pragma unroll
    for (int j = 0; j < 11; ++j) b0[j] = (xv >= g[j] && xv < g[j + 1]) ? 1.f : 0.f;
    float b1[10];
#pragma unroll
    for (int j = 0; j < 10; ++j)
        b1[j] = (xv - g[j]) / (g[j + 1] - g[j] + 1e-8f) * b0[j]
              + (g[j + 2] - xv) / (g[j + 2] - g[j + 1] + 1e-8f) * b0[j + 1];
    float b2[9];
#pragma unroll
    for (int j = 0; j < 9; ++j)
        b2[j] = (xv - g[j]) / (g[j + 2] - g[j] + 1e-8f) * b1[j]
              + (g[j + 3] - xv) / (g[j + 3] - g[j + 1] + 1e-8f) * b1[j + 1];
    float b3[8];
#pragma unroll
    for (int j = 0; j < 8; ++j)
        b3[j] = (xv - g[j]) / (g[j + 3] - g[j] + 1e-8f) * b2[j]
              + (g[j + 4] - xv) / (g[j + 4] - g[j + 1] + 1e-8f) * b2[j + 1];

    size_t rowoff = (size_t)b * KTOT;
    g_A[rowoff + i] = __float2half_rn(xv);

    __half h[8];
#pragma unroll
    for (int c = 0; c < 8; ++c) h[c] = __float2half_rn(b3[c]);
    *(uint4*)(g_A + rowoff + INDIM + (size_t)i * 8) = *(const uint4*)h;
}

// ---------------- stage loader: A 256x128B + W 256x128B, SW128 swizzled ----------------
__device__ __forceinline__ void load_stage(int kt, int m0, int o0, uint32_t stg, int tid) {
    size_t kcol = (size_t)kt * BK;
#pragma unroll
    for (int it = 0; it < 8; ++it) {          // 2048 16B-chunks per operand
        int idx = tid + it * 256;
        int r = idx >> 3, c = idx & 7;        // r in 0..255
        uint32_t off = (uint32_t)(r * 128 + c * 16);
        uint32_t sw = off ^ ((off >> 3) & 0x70);
        cp_async16(stg + sw, g_A + (size_t)(m0 + r) * KTOT + kcol + (size_t)c * 8);
        cp_async16(stg + STG_B_OFF + sw,
                   g_W + (size_t)(o0 + r) * KTOT + kcol + (size_t)c * 8);
    }
}

#if HAS_TC
// ================= tcgen05 path helpers (R13-validated) =================
__device__ __forceinline__ uint32_t elect1() {
    uint32_t r;
    asm volatile("{ .reg .pred p; elect.sync _|p, 0xFFFFFFFF; selp.b32 %0, 1, 0, p; }" : "=r"(r));
    return r;
}
__device__ __forceinline__ void mbar_init(uint32_t a, uint32_t cnt) {
    asm volatile("mbarrier.init.shared.b64 [%0], %1;" :: "r"(a), "r"(cnt) : "memory");
}
__device__ __forceinline__ void mbar_wait(uint32_t a, uint32_t parity) {
    asm volatile(
        "{\n\t.reg .pred P1;\n\t"
        "W_%=:\n\t"
        "mbarrier.try_wait.parity.acquire.cta.shared::cta.b64 P1, [%0], %1, 0x989680;\n\t"
        "@P1 bra.uni D_%=;\n\t"
        "bra.uni W_%=;\n\t"
        "D_%=:\n\t}"
        :: "r"(a), "r"(parity) : "memory");
}
__device__ __forceinline__ uint64_t mk_desc(uint32_t addr) {
    return ((uint64_t)2 << 61) | ((uint64_t)1 << 46) | ((uint64_t)64 << 32)
         | ((uint64_t)1 << 16) | ((uint64_t)(addr >> 4) & 0x3FFF);
}
#define IDESC 0x08200010u   // F32 accum, f16 x f16, N=128, M=128 (R13-proven)
__device__ __forceinline__ void mma_f16_ss(uint32_t d, uint64_t a, uint64_t b, uint32_t en) {
    asm volatile(
        "{\n\t.reg .pred p;\n\tsetp.ne.u32 p, %4, 0;\n\t"
        "tcgen05.mma.cta_group::1.kind::f16 [%0], %1, %2, %3, {%5,%5,%5,%5}, p;\n\t}"
        :: "r"(d), "l"(a), "l"(b), "r"(IDESC), "r"(en), "r"(0u) : "memory");
}
__device__ __forceinline__ void tmem_ld32(uint32_t* r, uint32_t addr) {
    asm volatile(
        "tcgen05.ld.sync.aligned.32x32b.x32.b32 "
        "{%0, %1, %2, %3, %4, %5, %6, %7, "
        " %8, %9, %10, %11, %12, %13, %14, %15, "
        " %16, %17, %18, %19, %20, %21, %22, %23, "
        " %24, %25, %26, %27, %28, %29, %30, %31}, [%32];"
        : "=r"(r[0]),  "=r"(r[1]),  "=r"(r[2]),  "=r"(r[3]),
          "=r"(r[4]),  "=r"(r[5]),  "=r"(r[6]),  "=r"(r[7]),
          "=r"(r[8]),  "=r"(r[9]),  "=r"(r[10]), "=r"(r[11]),
          "=r"(r[12]), "=r"(r[13]), "=r"(r[14]), "=r"(r[15]),
          "=r"(r[16]), "=r"(r[17]), "=r"(r[18]), "=r"(r[19]),
          "=r"(r[20]), "=r"(r[21]), "=r"(r[22]), "=r"(r[23]),
          "=r"(r[24]), "=r"(r[25]), "=r"(r[26]), "=r"(r[27]),
          "=r"(r[28]), "=r"(r[29]), "=r"(r[30]), "=r"(r[31])
        : "r"(addr));
}
#endif

// ---------------- GEMM: C[4096,2048] = A @ W^T, fp32 accum ----------------
__global__ void __launch_bounds__(256, 1)
gemm_kernel(float* __restrict__ out) {
    extern __shared__ char smem[];
    uint32_t sb = smem_u32(smem);
    uint32_t tiles = (sb + 64 + 1023) & ~1023u;
    int tid = threadIdx.x;
    int wid = tid >> 5;
    int lane = tid & 31;
    int m0 = blockIdx.y * BM;
    int o0 = blockIdx.x * BN;

#if HAS_TC
    if (wid == 0)
        asm volatile("tcgen05.alloc.cta_group::1.sync.aligned.shared::cta.b32 [%0], %1;"
                     :: "r"(sb), "r"(512u) : "memory");
    if (tid == 0) { mbar_init(sb + 8, 1); mbar_init(sb + 16, 1); }
    __syncthreads();
    uint32_t tmem;
    asm volatile("ld.shared.b32 %0, [%1];" : "=r"(tmem) : "r"(sb));

    load_stage(0, m0, o0, tiles, tid); CP_COMMIT();
    load_stage(1, m0, o0, tiles + STG_BYTES, tid); CP_COMMIT();

    uint32_t ph0 = 0, ph1 = 0;
    for (int kt = 0; kt < NKT; ++kt) {
        CP_WAIT1();
        __syncthreads();
        if (wid == 0 && elect1()) {
            asm volatile("fence.proxy.async.shared::cta;" ::: "memory");
            uint32_t stg = tiles + (uint32_t)(kt % NSTG) * STG_BYTES;
            uint64_t da0 = mk_desc(stg);
            uint64_t da1 = mk_desc(stg + 16384);                 // A rows 128..255
            uint64_t db0 = mk_desc(stg + STG_B_OFF);
            uint64_t db1 = mk_desc(stg + STG_B_OFF + 16384);     // W rows 128..255
#pragma unroll
            for (int ks = 0; ks < 4; ++ks) {
                uint64_t d = (uint64_t)(ks * 2);
                uint32_t en = (kt == 0 && ks == 0) ? 0u : 1u;
                mma_f16_ss(tmem +   0, da0 + d, db0 + d, en);
                mma_f16_ss(tmem + 128, da0 + d, db1 + d, en);
                mma_f16_ss(tmem + 256, da1 + d, db0 + d, en);
                mma_f16_ss(tmem + 384, da1 + d, db1 + d, en);
            }
            asm volatile(
                "tcgen05.commit.cta_group::1.mbarrier::arrive::one.shared::cluster.b64 [%0];"
                :: "r"(sb + 8 + (uint32_t)(kt & 1) * 8) : "memory");
        }
        if (kt > 0) {
            if ((kt - 1) & 1) { mbar_wait(sb + 16, ph1); ph1 ^= 1; }
            else              { mbar_wait(sb + 8,  ph0); ph0 ^= 1; }
        }
        if (kt + 2 < NKT)
            load_stage(kt + 2, m0, o0, tiles + (uint32_t)((kt + 2) % NSTG) * STG_BYTES, tid);
        CP_COMMIT();
    }
    if ((NKT - 1) & 1) mbar_wait(sb + 16, ph1);
    else               mbar_wait(sb + 8,  ph0);
    asm volatile("tcgen05.fence::after_thread_sync;" ::: "memory");

    // epilogue: warp w -> m-half h=w>>2 (TMEM cols h*256..+255), rows (w&3)*32+lane
    {
        int sub = wid & 3;
        int h = wid >> 2;
        float* orow = out + (size_t)(m0 + h * 128 + sub * 32 + lane) * OUTDIM + o0;
        uint32_t cbase = tmem + (uint32_t)(h * 256);
#pragma unroll
        for (int ch = 0; ch < 8; ++ch) {
            uint32_t r[32];
            tmem_ld32(r, cbase + (uint32_t)(ch * 32));
            asm volatile("tcgen05.wait::ld.sync.aligned;" ::: "memory");
#pragma unroll
            for (int q = 0; q < 8; ++q) {
                float4 v;
                v.x = __uint_as_float(r[q * 4 + 0]);
                v.y = __uint_as_float(r[q * 4 + 1]);
                v.z = __uint_as_float(r[q * 4 + 2]);
                v.w = __uint_as_float(r[q * 4 + 3]);
                *(float4*)(orow + ch * 32 + q * 4) = v;
            }
        }
    }
    asm volatile("tcgen05.fence::before_thread_sync;" ::: "memory");
    __syncthreads();
    if (wid == 0) {
        asm volatile("tcgen05.relinquish_alloc_permit.cta_group::1.sync.aligned;");
        asm volatile("tcgen05.dealloc.cta_group::1.sync.aligned.b32 %0, %1;"
                     :: "r"(tmem), "r"(512u));
    }
#else
    // ---- naive fallback (dead code: sm_103a SASS path is what executes; R10-R13 evidence)
    (void)sb; (void)tiles; (void)wid; (void)lane;
    for (int e = tid; e < BM * BN; e += 256) {
        int r = e / BN, c = e % BN;
        const __half* ar = g_A + (size_t)(m0 + r) * KTOT;
        const __half* wr = g_W + (size_t)(o0 + c) * KTOT;
        float s = 0.f;
        for (int k = 0; k < KTOT; ++k)
            s += __half2float(ar[k]) * __half2float(wr[k]);
        out[(size_t)(m0 + r) * OUTDIM + o0 + c] = s;
    }
#endif
}

// ---------------- launcher ----------------
extern "C" void kernel_launch(void* const* d_in, const int* in_sizes, int n_in,
                              void* d_out, int out_size) {
    (void)in_sizes; (void)n_in; (void)out_size;
    const float* x    = (const float*)d_in[0];
    const float* bw   = (const float*)d_in[1];
    const float* sw   = (const float*)d_in[2];
    const float* grid = (const float*)d_in[3];
    float* out = (float*)d_out;

    {
        int total4 = (OUTDIM * KTOT) / 4;
        wprep_kernel<<<(total4 + 255) / 256, 256>>>(bw, sw);
    }
    {
        int total = BDIM * INDIM;
        aprep_kernel<<<(total + 255) / 256, 256>>>(x, grid);
    }
    cudaFuncSetAttribute(gemm_kernel, cudaFuncAttributeMaxDynamicSharedMemorySize, SMEM_BYTES);
    dim3 g(OUTDIM / BN, BDIM / BM);   // (8, 16) = 128 CTAs, one wave
    gemm_kernel<<<g, 256, SMEM_BYTES>>>(out);
}